// round 15
// baseline (speedup 1.0000x reference)
#include <cuda_runtime.h>
#include <stdint.h>
#include <math.h>

#define BB 16
#define NTOT 21824
#define TOPN 1000
#define MAXOBJ 100
#define CAND_CAP 4096
#define NBUCKET 16384      // score < 1.0 -> (bits>>16) <= 0x3F7F < 16384
#define DPITCH 84          // smem row pitch (floats); %4==0 -> .128 conflict-free both ways

// ---------------- scratch (static device globals; zero-initialized at load) ----------------
__device__ uint32_t d_scoreBits[BB * NTOT];
__device__ int      d_cls[BB * NTOT];
__device__ uint32_t d_hist[BB * NBUCKET];          // cleared by k_select after use
__device__ float    d_topS[BB * TOPN];
__device__ int      d_topC[BB * TOPN];
__device__ float4   d_topB[BB * TOPN];
__device__ float    d_area[BB * TOPN];
__device__ uint32_t d_validW[BB * 32];
__device__ uint32_t d_mask[BB * TOPN * 32];        // zero rows are never written (stay 0)
__device__ uint32_t d_rnz[BB * 32];                // row-has-nonzero-mask bitmap

struct Ptrs {
    const float* cls[5];
    const float* reg[5];
    const float* ctr[5];
    const float* pos[5];
};

__constant__ int c_HW[5]   = {16384, 4096, 1024, 256, 64};
__constant__ int c_SH[5]   = {14, 12, 10, 8, 6};          // log2(HW)
__constant__ int c_OFF[5]  = {0, 16384, 20480, 21504, 21760};

// ---------------- decode: thread per anchor via SMEM transpose; no warp collectives ----------------
__global__ void __launch_bounds__(128) k_decode(Ptrs p) {
    __shared__ float sm[128 * DPITCH];   // 43008 B
    int blk = blockIdx.x;
    int t = threadIdx.x;

    int lvl, fStart;
    if (blk < 2048)      { lvl = 0; fStart = blk * 128; }
    else if (blk < 2560) { lvl = 1; fStart = (blk - 2048) * 128; }
    else if (blk < 2688) { lvl = 2; fStart = (blk - 2560) * 128; }
    else if (blk < 2720) { lvl = 3; fStart = (blk - 2688) * 128; }
    else                 { lvl = 4; fStart = (blk - 2720) * 128; }

    // stage 128 anchors x 80 floats, coalesced float4 loads
    const float4* src = (const float4*)(p.cls[lvl] + (size_t)fStart * 80);
    #pragma unroll
    for (int i = 0; i < 20; i++) {
        int idx = i * 128 + t;           // float4 index in chunk (20 per anchor)
        float4 v = src[idx];
        int a  = idx / 20;
        int k4 = idx - a * 20;
        *(float4*)&sm[a * DPITCH + k4 * 4] = v;
    }
    int f = fStart + t;
    float ctr = p.ctr[lvl][f];
    __syncthreads();

    // per-thread argmax over 80 values: 4 independent chains, exact first-index tiebreak
    const float* row = &sm[t * DPITCH];
    float m0 = -1.f, m1 = -1.f, m2 = -1.f, m3 = -1.f;
    int   i0 = 0, i1 = 1, i2 = 2, i3 = 3;
    #pragma unroll
    for (int j = 0; j < 20; j++) {
        float4 v = *(const float4*)&row[4 * j];
        if (v.x > m0) { m0 = v.x; i0 = 4 * j; }
        if (v.y > m1) { m1 = v.y; i1 = 4 * j + 1; }
        if (v.z > m2) { m2 = v.z; i2 = 4 * j + 2; }
        if (v.w > m3) { m3 = v.w; i3 = 4 * j + 3; }
    }
    float m = m0; int mi = i0;
    if (m1 > m || (m1 == m && i1 < mi)) { m = m1; mi = i1; }
    if (m2 > m || (m2 == m && i2 < mi)) { m = m2; mi = i2; }
    if (m3 > m || (m3 == m && i3 < mi)) { m = m3; mi = i3; }

    int b  = f >> c_SH[lvl];
    int hw = f - (b << c_SH[lvl]);
    int g  = b * NTOT + c_OFF[lvl] + hw;
    float s = __fsqrt_rn(m * ctr);
    uint32_t bits = __float_as_uint(s);
    d_scoreBits[g] = bits;
    d_cls[g] = mi;
    uint32_t bk = bits >> 16;
    if (bk >= NBUCKET) bk = NBUCKET - 1;
    atomicAdd(&d_hist[b * NBUCKET + bk], 1u);
}

// ---------------- per-batch: pivot + collect + sort + emit top-1000 (gathers boxes) ----------------
__global__ void __launch_bounds__(1024, 1) k_select(Ptrs p) {
    __shared__ unsigned long long sk[CAND_CAP];
    __shared__ uint32_t sSuf[1024];
    __shared__ uint32_t sWarpTot[32];
    __shared__ uint32_t svalid[32];
    __shared__ uint32_t shCnt;
    __shared__ uint32_t shPivot;
    __shared__ int shChunk;

    int b = blockIdx.x;
    int t = threadIdx.x;   // 1024
    int lane = t & 31, w = t >> 5;
    uint32_t* h = &d_hist[b * NBUCKET];

    #pragma unroll
    for (int i = t; i < CAND_CAP; i += 1024) sk[i] = 0ULL;
    if (t == 0) shCnt = 0u;
    if (t < 32) { svalid[t] = 0u; d_rnz[b * 32 + t] = 0u; }

    // chunk sums: thread t owns buckets [t*16, t*16+16)
    uint32_t chunkSum;
    {
        uint32_t s = 0;
        const uint4* hv = (const uint4*)(h + t * 16);
        #pragma unroll
        for (int q = 0; q < 4; q++) {
            uint4 v = hv[q];
            s += v.x + v.y + v.z + v.w;
        }
        chunkSum = s;
    }

    // two-level suffix scan (inclusive, toward higher index): in-warp via shfl_down
    uint32_t inWarp = chunkSum;
    #pragma unroll
    for (int off = 1; off < 32; off <<= 1) {
        uint32_t n = __shfl_down_sync(0xffffffffu, inWarp, off);
        if (lane + off < 32) inWarp += n;
    }
    if (lane == 0) sWarpTot[w] = inWarp;   // warp total = suffix at lane 0
    __syncthreads();
    // warp 0: suffix over warp totals, exclusive-after (sum of totals of warps > w)
    if (t < 32) {
        uint32_t wt = sWarpTot[t];
        uint32_t suf = wt;
        #pragma unroll
        for (int off = 1; off < 32; off <<= 1) {
            uint32_t n = __shfl_down_sync(0xffffffffu, suf, off);
            if (t + off < 32) suf += n;
        }
        uint32_t after = __shfl_down_sync(0xffffffffu, suf, 1);
        if (t == 31) after = 0u;
        sWarpTot[t] = after;               // sum of chunk sums in warps after t
    }
    __syncthreads();
    uint32_t suffix = inWarp + sWarpTot[w];   // inclusive suffix from chunk t upward
    sSuf[t] = suffix;
    __syncthreads();

    // find largest chunk c with suffix >= TOPN
    if (suffix >= TOPN && (t == 1023 || sSuf[t + 1] < TOPN)) shChunk = t;
    __syncthreads();
    if (t == 0) {
        int c = shChunk;
        uint32_t run = (c < 1023) ? sSuf[c + 1] : 0u;
        uint32_t piv = (uint32_t)(c * 16);
        for (int v = c * 16 + 15; v >= c * 16; v--) {
            run += h[v];
            if (run >= TOPN) { piv = (uint32_t)v; break; }
        }
        shPivot = piv;
    }
    __syncthreads();
    uint32_t pivot = shPivot;

    // zero hist slice for next replay
    {
        uint4 z = make_uint4(0u, 0u, 0u, 0u);
        ((uint4*)(h + t * 16))[0] = z;
        ((uint4*)(h + t * 16))[1] = z;
        ((uint4*)(h + t * 16))[2] = z;
        ((uint4*)(h + t * 16))[3] = z;
    }

    // collect candidates >= pivot into shared
    const uint32_t* sbits = &d_scoreBits[b * NTOT];
    for (int i = t; i < NTOT; i += 1024) {
        uint32_t bits = sbits[i];
        if ((bits >> 16) >= pivot) {
            uint32_t slot = atomicAdd(&shCnt, 1u);
            if (slot < CAND_CAP)
                sk[slot] = ((unsigned long long)bits << 15) |
                           (unsigned long long)(32767 - i);
        }
    }
    __syncthreads();

    uint32_t cnt = shCnt;
    if (cnt > CAND_CAP) cnt = CAND_CAP;
    int sortN = 1024;
    while (sortN < (int)cnt) sortN <<= 1;

    // bitonic sort, descending
    for (int k = 2; k <= sortN; k <<= 1) {
        for (int j = k >> 1; j > 0; j >>= 1) {
            for (int i = t; i < sortN; i += 1024) {
                int ix = i ^ j;
                if (ix > i) {
                    bool dir = ((i & k) == 0);
                    unsigned long long A = sk[i], Bv = sk[ix];
                    if ((A < Bv) == dir) { sk[i] = Bv; sk[ix] = A; }
                }
            }
            __syncthreads();
        }
    }

    // emit top-1000: gather reg/pos for winners and build boxes here
    if (t < TOPN) {
        unsigned long long key = sk[t];
        float s; int c; float4 bx;
        int a = 32767 - (int)(key & 0x7FFFULL);
        if (key == 0ULL || a < 0 || a >= NTOT) {
            s = -1e30f; c = 0; bx = make_float4(0.f, 0.f, 0.f, 0.f);
        } else {
            s = __uint_as_float((uint32_t)(key >> 15));
            c = d_cls[b * NTOT + a];
            int lvl, hw;
            if (a < 16384)      { lvl = 0; hw = a; }
            else if (a < 20480) { lvl = 1; hw = a - 16384; }
            else if (a < 21504) { lvl = 2; hw = a - 20480; }
            else if (a < 21760) { lvl = 3; hw = a - 21504; }
            else                { lvl = 4; hw = a - 21760; }
            int base = b * c_HW[lvl] + hw;
            float4 rr = ((const float4*)p.reg[lvl])[base];
            float2 pp = ((const float2*)p.pos[lvl])[base];
            bx.x = truncf(pp.x - rr.x);
            bx.y = truncf(pp.y - rr.y);
            bx.z = truncf(pp.x + rr.z);
            bx.w = truncf(pp.y + rr.w);
        }
        d_topS[b * TOPN + t] = s;
        d_topC[b * TOPN + t] = c;
        d_topB[b * TOPN + t] = bx;
        float w2 = bx.z - bx.x, hh = bx.w - bx.y;
        d_area[b * TOPN + t] = fmaxf(w2 * hh, 1e-4f);
        if (s > 0.05f) atomicOr(&svalid[t >> 5], 1u << (t & 31));
    }
    __syncthreads();
    if (t < 32) d_validW[b * 32 + t] = svalid[t];
}

// ---------------- IoU mask matrix: grid (B, 32), 1024 threads ----------------
__global__ void __launch_bounds__(1024, 1) k_mask() {
    __shared__ float4 sb[TOPN];
    __shared__ float  sa[TOPN];
    __shared__ uint32_t sv[32];
    int b = blockIdx.x;
    int rb = blockIdx.y;
    int t = threadIdx.x;
    for (int i = t; i < TOPN; i += 1024) {
        sb[i] = d_topB[b * TOPN + i];
        sa[i] = d_area[b * TOPN + i];
    }
    if (t < 32) sv[t] = d_validW[b * 32 + t];
    __syncthreads();

    int lane = t & 31, w = t >> 5;
    int rbase = rb * 32;
    int rend = rbase + 32; if (rend > TOPN) rend = TOPN;
    for (int i = rbase + w; i < rend; i += 32) {
        bool vi = (sv[i >> 5] >> (i & 31)) & 1u;
        if (!vi) continue;   // whole row is zero; never written, stays 0
        float4 bi = sb[i];
        float ai = sa[i];
        uint32_t anyrow = 0u;
        int jw0 = i >> 5;
        #pragma unroll 4
        for (int jw = jw0; jw < 32; jw++) {
            int j = jw * 32 + lane;
            bool pred = false;
            if (j < TOPN && j > i) {
                float tlx = fmaxf(bi.x, sb[j].x), tly = fmaxf(bi.y, sb[j].y);
                float brx = fminf(bi.z, sb[j].z), bry = fminf(bi.w, sb[j].w);
                float ow = fmaxf(brx - tlx, 0.f), oh = fmaxf(bry - tly, 0.f);
                float inter = ow * oh;
                float uni = fmaxf(ai + sa[j] - inter, 1e-4f);
                pred = (inter / uni) >= 0.6f;
            }
            uint32_t m = __ballot_sync(0xffffffffu, pred);
            anyrow |= m;
            if (lane == 0) d_mask[(b * TOPN + i) * 32 + jw] = m;
        }
        if (lane == 0 && anyrow)
            atomicOr(&d_rnz[b * 32 + (i >> 5)], 1u << (i & 31));
    }
}

// ---------------- serial suppression + output scatter: grid B, 512 threads ----------------
__global__ void __launch_bounds__(512, 1) k_nms(float* out) {
    extern __shared__ uint32_t shm[];            // compacted rows: nrnz x 32 words
    __shared__ uint32_t sRnz[32];
    __shared__ uint32_t sBase[33];
    __shared__ uint16_t rowOfSlot[TOPN];
    int b = blockIdx.x;
    int t = threadIdx.x;
    int lane = t & 31;

    if (t < 32) sRnz[t] = d_rnz[b * 32 + t];

    // init outputs for this batch
    for (int k = t; k < 100; k += 512) {
        out[b * 100 + k] = -1.0f;               // scores
        out[1600 + b * 100 + k] = -1.0f;        // classes
    }
    for (int k = t; k < 400; k += 512)
        out[3200 + b * 400 + k] = 0.0f;         // boxes
    __syncthreads();

    // warp 0: exclusive scan of popcounts -> sBase
    if (t < 32) {
        int pc = __popc(sRnz[t]);
        int pre = pc;
        #pragma unroll
        for (int off = 1; off < 32; off <<= 1) {
            int n = __shfl_up_sync(0xffffffffu, pre, off);
            if (t >= off) pre += n;
        }
        sBase[t] = (uint32_t)(pre - pc);
        if (t == 31) sBase[32] = (uint32_t)pre;
    }
    __syncthreads();
    int nrnz = (int)sBase[32];

    // parallel slot map: strided over all TOPN rows
    for (int i = t; i < TOPN; i += 512) {
        uint32_t wbits = sRnz[i >> 5];
        if ((wbits >> (i & 31)) & 1u) {
            int slot = (int)sBase[i >> 5] + __popc(wbits & ((1u << (i & 31)) - 1u));
            rowOfSlot[slot] = (uint16_t)i;
        }
    }
    __syncthreads();

    // stage compacted rows: uint4-coalesced, all 512 threads
    {
        uint4* shv = (uint4*)shm;
        const uint4* gm = (const uint4*)&d_mask[b * TOPN * 32];
        int tot = nrnz * 8;
        for (int i = t; i < tot; i += 512)
            shv[i] = gm[(int)rowOfSlot[i >> 3] * 8 + (i & 7)];
    }
    __syncthreads();

    if (t >= 32) return;  // warp 0 only from here

    uint32_t myRnz = sRnz[lane];
    uint32_t myBase = sBase[lane];

    // diagonal prefetch: dwreg[bw] = row (bw*32+lane)'s word bw (0 if row has no mask)
    uint32_t dwreg[32];
    #pragma unroll
    for (int bw = 0; bw < 32; bw++) {
        uint32_t rw = sRnz[bw];
        uint32_t has = (rw >> lane) & 1u;
        uint32_t slot = sBase[bw] + __popc(rw & ((1u << lane) - 1u));
        dwreg[bw] = has ? shm[slot * 32 + bw] : 0u;
    }

    uint32_t supp = 0;
    for (int bw = 0; bw < 32; bw++) {
        uint32_t sw = __shfl_sync(0xffffffffu, supp, bw);
        uint32_t dw = dwreg[bw];
        uint32_t conflict = __ballot_sync(0xffffffffu, dw != 0u) & ~sw;
        uint32_t active;
        if (!conflict) {
            active = ~sw;
        } else {
            active = ~sw;
            uint32_t rem = conflict;
            while (rem) {
                int hrow = __ffs(rem) - 1;
                rem &= rem - 1;
                uint32_t dwh = __shfl_sync(0xffffffffu, dw, hrow);
                if ((active >> hrow) & 1u) {
                    active &= ~dwh;
                    rem &= ~dwh;
                }
            }
        }
        if (bw == 31) active &= 0xFFu;   // rows >= 1000 don't exist
        uint32_t rz = __shfl_sync(0xffffffffu, myRnz, bw);
        uint32_t bbase = __shfl_sync(0xffffffffu, myBase, bw);
        uint32_t need = active & rz;
        while (need) {
            int r0 = __ffs(need) - 1;
            need &= need - 1;
            uint32_t s0 = bbase + __popc(rz & ((1u << r0) - 1u));
            uint32_t v = shm[s0 * 32 + lane];
            if (need) {
                int r1 = __ffs(need) - 1;
                need &= need - 1;
                uint32_t s1 = bbase + __popc(rz & ((1u << r1) - 1u));
                v |= shm[s1 * 32 + lane];
            }
            supp |= v;
        }
    }

    uint32_t kw = d_validW[b * 32 + lane] & ~supp;

    // exclusive scan of keep-counts across lanes
    int pc = __popc(kw);
    int pre = pc;
    #pragma unroll
    for (int off = 1; off < 32; off <<= 1) {
        int n = __shfl_up_sync(0xffffffffu, pre, off);
        if (lane >= off) pre += n;
    }
    int r = pre - pc;

    uint32_t wv = kw;
    while (wv) {
        int bit = __ffs(wv) - 1;
        wv &= wv - 1;
        if (r < MAXOBJ) {
            int i = lane * 32 + bit;
            out[b * 100 + r] = d_topS[b * TOPN + i];
            out[1600 + b * 100 + r] = (float)d_topC[b * TOPN + i];
            float4 bx = d_topB[b * TOPN + i];
            float* ob = out + 3200 + (b * 100 + r) * 4;
            ob[0] = bx.x; ob[1] = bx.y; ob[2] = bx.z; ob[3] = bx.w;
        }
        r++;
    }
}

// ---------------- host launch ----------------
extern "C" void kernel_launch(void* const* d_in, const int* in_sizes, int n_in,
                              void* d_out, int out_size) {
    (void)n_in; (void)out_size;
    const int HW0 = 16384;
    Ptrs P;
    bool dictOrder = (in_sizes[1] == BB * HW0 * 4);  // reg0 right after cls0?
    if (dictOrder) {
        for (int l = 0; l < 5; l++) {
            P.cls[l] = (const float*)d_in[l * 4 + 0];
            P.reg[l] = (const float*)d_in[l * 4 + 1];
            P.ctr[l] = (const float*)d_in[l * 4 + 2];
            P.pos[l] = (const float*)d_in[l * 4 + 3];
        }
    } else {
        for (int l = 0; l < 5; l++) {
            P.cls[l] = (const float*)d_in[l];
            P.reg[l] = (const float*)d_in[5 + l];
            P.ctr[l] = (const float*)d_in[10 + l];
            P.pos[l] = (const float*)d_in[15 + l];
        }
    }

    float* out = (float*)d_out;

    static const size_t NMS_SHM = (size_t)TOPN * 32 * sizeof(uint32_t);
    cudaFuncSetAttribute(k_nms, cudaFuncAttributeMaxDynamicSharedMemorySize,
                         (int)NMS_SHM);

    // decode: per-level block counts 2048/512/128/32/8 = 2728 blocks of 128
    k_decode<<<2728, 128>>>(P);
    k_select<<<BB, 1024>>>(P);
    dim3 mg(BB, 32);
    k_mask<<<mg, 1024>>>();
    k_nms<<<BB, 512, NMS_SHM>>>(out);
}

// round 16
// speedup vs baseline: 1.4699x; 1.4699x over previous
#include <cuda_runtime.h>
#include <stdint.h>
#include <math.h>

#define BB 16
#define NTOT 21824
#define TOPN 1000
#define MAXOBJ 100
#define CAND_CAP 4096
#define NBUCKET 16384      // score < 1.0 -> (bits>>16) <= 0x3F7F < 16384
#define DPITCH 84          // smem row pitch (floats); %4==0 -> .128 conflict-free both ways

// ---------------- scratch (static device globals; zero-initialized at load) ----------------
__device__ uint32_t d_scoreBits[BB * NTOT];
__device__ int      d_cls[BB * NTOT];
__device__ uint32_t d_hist[BB * NBUCKET];          // cleared by k_select after use
__device__ float    d_topS[BB * TOPN];
__device__ int      d_topC[BB * TOPN];
__device__ float4   d_topB[BB * TOPN];
__device__ float    d_area[BB * TOPN];
__device__ uint32_t d_validW[BB * 32];
__device__ uint32_t d_mask[BB * TOPN * 32];        // zero rows are never written (stay 0)
__device__ uint32_t d_rnz[BB * 32];                // row-has-nonzero-mask bitmap

struct Ptrs {
    const float* cls[5];
    const float* reg[5];
    const float* ctr[5];
    const float* pos[5];
};

__constant__ int c_HW[5]   = {16384, 4096, 1024, 256, 64};
__constant__ int c_SH[5]   = {14, 12, 10, 8, 6};          // log2(HW)
__constant__ int c_OFF[5]  = {0, 16384, 20480, 21504, 21760};

// ---------------- decode: thread per anchor via SMEM transpose; no warp collectives ----------------
__global__ void __launch_bounds__(128) k_decode(Ptrs p) {
    __shared__ float sm[128 * DPITCH];   // 43008 B
    int blk = blockIdx.x;
    int t = threadIdx.x;

    int lvl, fStart;
    if (blk < 2048)      { lvl = 0; fStart = blk * 128; }
    else if (blk < 2560) { lvl = 1; fStart = (blk - 2048) * 128; }
    else if (blk < 2688) { lvl = 2; fStart = (blk - 2560) * 128; }
    else if (blk < 2720) { lvl = 3; fStart = (blk - 2688) * 128; }
    else                 { lvl = 4; fStart = (blk - 2720) * 128; }

    // stage 128 anchors x 80 floats, coalesced float4 loads
    const float4* src = (const float4*)(p.cls[lvl] + (size_t)fStart * 80);
    #pragma unroll
    for (int i = 0; i < 20; i++) {
        int idx = i * 128 + t;           // float4 index in chunk (20 per anchor)
        float4 v = src[idx];
        int a  = idx / 20;
        int k4 = idx - a * 20;
        *(float4*)&sm[a * DPITCH + k4 * 4] = v;
    }
    int f = fStart + t;
    float ctr = p.ctr[lvl][f];
    __syncthreads();

    // per-thread argmax over 80 values: 4 independent chains, exact first-index tiebreak
    const float* row = &sm[t * DPITCH];
    float m0 = -1.f, m1 = -1.f, m2 = -1.f, m3 = -1.f;
    int   i0 = 0, i1 = 1, i2 = 2, i3 = 3;
    #pragma unroll
    for (int j = 0; j < 20; j++) {
        float4 v = *(const float4*)&row[4 * j];
        if (v.x > m0) { m0 = v.x; i0 = 4 * j; }
        if (v.y > m1) { m1 = v.y; i1 = 4 * j + 1; }
        if (v.z > m2) { m2 = v.z; i2 = 4 * j + 2; }
        if (v.w > m3) { m3 = v.w; i3 = 4 * j + 3; }
    }
    float m = m0; int mi = i0;
    if (m1 > m || (m1 == m && i1 < mi)) { m = m1; mi = i1; }
    if (m2 > m || (m2 == m && i2 < mi)) { m = m2; mi = i2; }
    if (m3 > m || (m3 == m && i3 < mi)) { m = m3; mi = i3; }

    int b  = f >> c_SH[lvl];
    int hw = f - (b << c_SH[lvl]);
    int g  = b * NTOT + c_OFF[lvl] + hw;
    float s = __fsqrt_rn(m * ctr);
    uint32_t bits = __float_as_uint(s);
    d_scoreBits[g] = bits;
    d_cls[g] = mi;
    uint32_t bk = bits >> 16;
    if (bk >= NBUCKET) bk = NBUCKET - 1;
    atomicAdd(&d_hist[b * NBUCKET + bk], 1u);
}

// ---------------- per-batch: pivot + collect + sort + emit top-1000 (gathers boxes) ----------------
__global__ void __launch_bounds__(1024, 1) k_select(Ptrs p) {
    __shared__ unsigned long long sk[CAND_CAP];
    __shared__ uint32_t sA[1024], sB[1024];
    __shared__ uint32_t svalid[32];
    __shared__ uint32_t shCnt;
    __shared__ uint32_t shPivot;
    __shared__ int shChunk;

    int b = blockIdx.x;
    int t = threadIdx.x;   // 1024
    uint32_t* h = &d_hist[b * NBUCKET];

    #pragma unroll
    for (int i = t; i < CAND_CAP; i += 1024) sk[i] = 0ULL;
    if (t == 0) shCnt = 0u;
    if (t < 32) { svalid[t] = 0u; d_rnz[b * 32 + t] = 0u; }

    // chunk sums: thread t owns buckets [t*16, t*16+16)
    {
        uint32_t s = 0;
        const uint4* hv = (const uint4*)(h + t * 16);
        #pragma unroll
        for (int q = 0; q < 4; q++) {
            uint4 v = hv[q];
            s += v.x + v.y + v.z + v.w;
        }
        sA[t] = s;
    }
    __syncthreads();

    // parallel inclusive suffix scan over 1024 chunk sums (Hillis-Steele, ping-pong)
    uint32_t* src = sA; uint32_t* dst = sB;
    #pragma unroll
    for (int off = 1; off < 1024; off <<= 1) {
        uint32_t v = src[t] + ((t + off < 1024) ? src[t + off] : 0u);
        dst[t] = v;
        __syncthreads();
        uint32_t* tmp = src; src = dst; dst = tmp;
    }

    if (src[t] >= TOPN && (t == 1023 || src[t + 1] < TOPN)) shChunk = t;
    __syncthreads();
    if (t == 0) {
        int c = shChunk;
        uint32_t run = (c < 1023) ? src[c + 1] : 0u;
        uint32_t piv = (uint32_t)(c * 16);
        for (int v = c * 16 + 15; v >= c * 16; v--) {
            run += h[v];
            if (run >= TOPN) { piv = (uint32_t)v; break; }
        }
        shPivot = piv;
    }
    __syncthreads();
    uint32_t pivot = shPivot;

    // zero hist slice for next replay
    {
        uint4 z = make_uint4(0u, 0u, 0u, 0u);
        ((uint4*)(h + t * 16))[0] = z;
        ((uint4*)(h + t * 16))[1] = z;
        ((uint4*)(h + t * 16))[2] = z;
        ((uint4*)(h + t * 16))[3] = z;
    }

    // collect candidates >= pivot into shared
    const uint32_t* sbits = &d_scoreBits[b * NTOT];
    for (int i = t; i < NTOT; i += 1024) {
        uint32_t bits = sbits[i];
        if ((bits >> 16) >= pivot) {
            uint32_t slot = atomicAdd(&shCnt, 1u);
            if (slot < CAND_CAP)
                sk[slot] = ((unsigned long long)bits << 15) |
                           (unsigned long long)(32767 - i);
        }
    }
    __syncthreads();

    uint32_t cnt = shCnt;
    if (cnt > CAND_CAP) cnt = CAND_CAP;
    int sortN = 1024;
    while (sortN < (int)cnt) sortN <<= 1;

    // bitonic sort, descending
    for (int k = 2; k <= sortN; k <<= 1) {
        for (int j = k >> 1; j > 0; j >>= 1) {
            for (int i = t; i < sortN; i += 1024) {
                int ix = i ^ j;
                if (ix > i) {
                    bool dir = ((i & k) == 0);
                    unsigned long long A = sk[i], Bv = sk[ix];
                    if ((A < Bv) == dir) { sk[i] = Bv; sk[ix] = A; }
                }
            }
            __syncthreads();
        }
    }

    // emit top-1000: gather reg/pos for winners and build boxes here
    if (t < TOPN) {
        unsigned long long key = sk[t];
        float s; int c; float4 bx;
        int a = 32767 - (int)(key & 0x7FFFULL);
        if (key == 0ULL || a < 0 || a >= NTOT) {
            s = -1e30f; c = 0; bx = make_float4(0.f, 0.f, 0.f, 0.f);
        } else {
            s = __uint_as_float((uint32_t)(key >> 15));
            c = d_cls[b * NTOT + a];
            int lvl, hw;
            if (a < 16384)      { lvl = 0; hw = a; }
            else if (a < 20480) { lvl = 1; hw = a - 16384; }
            else if (a < 21504) { lvl = 2; hw = a - 20480; }
            else if (a < 21760) { lvl = 3; hw = a - 21504; }
            else                { lvl = 4; hw = a - 21760; }
            int base = b * c_HW[lvl] + hw;
            float4 rr = ((const float4*)p.reg[lvl])[base];
            float2 pp = ((const float2*)p.pos[lvl])[base];
            bx.x = truncf(pp.x - rr.x);
            bx.y = truncf(pp.y - rr.y);
            bx.z = truncf(pp.x + rr.z);
            bx.w = truncf(pp.y + rr.w);
        }
        d_topS[b * TOPN + t] = s;
        d_topC[b * TOPN + t] = c;
        d_topB[b * TOPN + t] = bx;
        float w = bx.z - bx.x, hh = bx.w - bx.y;
        d_area[b * TOPN + t] = fmaxf(w * hh, 1e-4f);
        if (s > 0.05f) atomicOr(&svalid[t >> 5], 1u << (t & 31));
    }
    __syncthreads();
    if (t < 32) d_validW[b * 32 + t] = svalid[t];
}

// ---------------- IoU mask matrix: grid (B, 32), 1024 threads ----------------
__global__ void __launch_bounds__(1024, 1) k_mask() {
    __shared__ float4 sb[TOPN];
    __shared__ float  sa[TOPN];
    __shared__ uint32_t sv[32];
    int b = blockIdx.x;
    int rb = blockIdx.y;
    int t = threadIdx.x;
    for (int i = t; i < TOPN; i += 1024) {
        sb[i] = d_topB[b * TOPN + i];
        sa[i] = d_area[b * TOPN + i];
    }
    if (t < 32) sv[t] = d_validW[b * 32 + t];
    __syncthreads();

    int lane = t & 31, w = t >> 5;
    int rbase = rb * 32;
    int rend = rbase + 32; if (rend > TOPN) rend = TOPN;
    for (int i = rbase + w; i < rend; i += 32) {
        bool vi = (sv[i >> 5] >> (i & 31)) & 1u;
        if (!vi) continue;   // whole row is zero; never written, stays 0
        float4 bi = sb[i];
        float ai = sa[i];
        uint32_t anyrow = 0u;
        int jw0 = i >> 5;
        #pragma unroll 4
        for (int jw = jw0; jw < 32; jw++) {
            int j = jw * 32 + lane;
            bool pred = false;
            if (j < TOPN && j > i) {
                float tlx = fmaxf(bi.x, sb[j].x), tly = fmaxf(bi.y, sb[j].y);
                float brx = fminf(bi.z, sb[j].z), bry = fminf(bi.w, sb[j].w);
                float ow = fmaxf(brx - tlx, 0.f), oh = fmaxf(bry - tly, 0.f);
                float inter = ow * oh;
                float uni = fmaxf(ai + sa[j] - inter, 1e-4f);
                pred = (inter / uni) >= 0.6f;
            }
            uint32_t m = __ballot_sync(0xffffffffu, pred);
            anyrow |= m;
            if (lane == 0) d_mask[(b * TOPN + i) * 32 + jw] = m;
        }
        if (lane == 0 && anyrow)
            atomicOr(&d_rnz[b * 32 + (i >> 5)], 1u << (i & 31));
    }
}

// ---------------- serial suppression + output scatter: grid B, 512 threads ----------------
__global__ void __launch_bounds__(512, 1) k_nms(float* out) {
    extern __shared__ uint32_t shm[];            // compacted rows: nrnz x 32 words
    __shared__ uint32_t sRnz[32];
    __shared__ uint32_t sBase[33];
    __shared__ uint16_t rowOfSlot[TOPN];
    int b = blockIdx.x;
    int t = threadIdx.x;
    int lane = t & 31;

    if (t < 32) sRnz[t] = d_rnz[b * 32 + t];

    // init outputs for this batch
    for (int k = t; k < 100; k += 512) {
        out[b * 100 + k] = -1.0f;               // scores
        out[1600 + b * 100 + k] = -1.0f;        // classes
    }
    for (int k = t; k < 400; k += 512)
        out[3200 + b * 400 + k] = 0.0f;         // boxes
    __syncthreads();

    // warp 0: exclusive scan of popcounts -> sBase
    if (t < 32) {
        int pc = __popc(sRnz[t]);
        int pre = pc;
        #pragma unroll
        for (int off = 1; off < 32; off <<= 1) {
            int n = __shfl_up_sync(0xffffffffu, pre, off);
            if (t >= off) pre += n;
        }
        sBase[t] = (uint32_t)(pre - pc);
        if (t == 31) sBase[32] = (uint32_t)pre;
    }
    __syncthreads();
    int nrnz = (int)sBase[32];

    // parallel slot map: strided over all TOPN rows
    for (int i = t; i < TOPN; i += 512) {
        uint32_t wbits = sRnz[i >> 5];
        if ((wbits >> (i & 31)) & 1u) {
            int slot = (int)sBase[i >> 5] + __popc(wbits & ((1u << (i & 31)) - 1u));
            rowOfSlot[slot] = (uint16_t)i;
        }
    }
    __syncthreads();

    // stage compacted rows: uint4-coalesced, all 512 threads
    {
        uint4* shv = (uint4*)shm;
        const uint4* gm = (const uint4*)&d_mask[b * TOPN * 32];
        int tot = nrnz * 8;
        for (int i = t; i < tot; i += 512)
            shv[i] = gm[(int)rowOfSlot[i >> 3] * 8 + (i & 7)];
    }
    __syncthreads();

    if (t >= 32) return;  // warp 0 only from here

    uint32_t myRnz = sRnz[lane];
    uint32_t myBase = sBase[lane];

    // diagonal prefetch: dwreg[bw] = row (bw*32+lane)'s word bw (0 if row has no mask)
    uint32_t dwreg[32];
    #pragma unroll
    for (int bw = 0; bw < 32; bw++) {
        uint32_t rw = sRnz[bw];
        uint32_t has = (rw >> lane) & 1u;
        uint32_t slot = sBase[bw] + __popc(rw & ((1u << lane) - 1u));
        dwreg[bw] = has ? shm[slot * 32 + bw] : 0u;
    }

    uint32_t supp = 0;
    for (int bw = 0; bw < 32; bw++) {
        uint32_t sw = __shfl_sync(0xffffffffu, supp, bw);
        uint32_t dw = dwreg[bw];
        uint32_t conflict = __ballot_sync(0xffffffffu, dw != 0u) & ~sw;
        uint32_t active;
        if (!conflict) {
            active = ~sw;
        } else {
            active = ~sw;
            uint32_t rem = conflict;
            while (rem) {
                int hrow = __ffs(rem) - 1;
                rem &= rem - 1;
                uint32_t dwh = __shfl_sync(0xffffffffu, dw, hrow);
                if ((active >> hrow) & 1u) {
                    active &= ~dwh;
                    rem &= ~dwh;
                }
            }
        }
        if (bw == 31) active &= 0xFFu;   // rows >= 1000 don't exist
        uint32_t rz = __shfl_sync(0xffffffffu, myRnz, bw);
        uint32_t bbase = __shfl_sync(0xffffffffu, myBase, bw);
        uint32_t need = active & rz;
        while (need) {
            int r0 = __ffs(need) - 1;
            need &= need - 1;
            uint32_t s0 = bbase + __popc(rz & ((1u << r0) - 1u));
            uint32_t v = shm[s0 * 32 + lane];
            if (need) {
                int r1 = __ffs(need) - 1;
                need &= need - 1;
                uint32_t s1 = bbase + __popc(rz & ((1u << r1) - 1u));
                v |= shm[s1 * 32 + lane];
            }
            supp |= v;
        }
    }

    uint32_t kw = d_validW[b * 32 + lane] & ~supp;

    // exclusive scan of keep-counts across lanes
    int pc = __popc(kw);
    int pre = pc;
    #pragma unroll
    for (int off = 1; off < 32; off <<= 1) {
        int n = __shfl_up_sync(0xffffffffu, pre, off);
        if (lane >= off) pre += n;
    }
    int r = pre - pc;

    uint32_t wv = kw;
    while (wv) {
        int bit = __ffs(wv) - 1;
        wv &= wv - 1;
        if (r < MAXOBJ) {
            int i = lane * 32 + bit;
            out[b * 100 + r] = d_topS[b * TOPN + i];
            out[1600 + b * 100 + r] = (float)d_topC[b * TOPN + i];
            float4 bx = d_topB[b * TOPN + i];
            float* ob = out + 3200 + (b * 100 + r) * 4;
            ob[0] = bx.x; ob[1] = bx.y; ob[2] = bx.z; ob[3] = bx.w;
        }
        r++;
    }
}

// ---------------- host launch ----------------
extern "C" void kernel_launch(void* const* d_in, const int* in_sizes, int n_in,
                              void* d_out, int out_size) {
    (void)n_in; (void)out_size;
    const int HW0 = 16384;
    Ptrs P;
    bool dictOrder = (in_sizes[1] == BB * HW0 * 4);  // reg0 right after cls0?
    if (dictOrder) {
        for (int l = 0; l < 5; l++) {
            P.cls[l] = (const float*)d_in[l * 4 + 0];
            P.reg[l] = (const float*)d_in[l * 4 + 1];
            P.ctr[l] = (const float*)d_in[l * 4 + 2];
            P.pos[l] = (const float*)d_in[l * 4 + 3];
        }
    } else {
        for (int l = 0; l < 5; l++) {
            P.cls[l] = (const float*)d_in[l];
            P.reg[l] = (const float*)d_in[5 + l];
            P.ctr[l] = (const float*)d_in[10 + l];
            P.pos[l] = (const float*)d_in[15 + l];
        }
    }

    float* out = (float*)d_out;

    static const size_t NMS_SHM = (size_t)TOPN * 32 * sizeof(uint32_t);
    cudaFuncSetAttribute(k_nms, cudaFuncAttributeMaxDynamicSharedMemorySize,
                         (int)NMS_SHM);

    // decode: per-level block counts 2048/512/128/32/8 = 2728 blocks of 128
    k_decode<<<2728, 128>>>(P);
    k_select<<<BB, 1024>>>(P);
    dim3 mg(BB, 32);
    k_mask<<<mg, 1024>>>();
    k_nms<<<BB, 512, NMS_SHM>>>(out);
}

// round 17
// speedup vs baseline: 1.5553x; 1.0581x over previous
#include <cuda_runtime.h>
#include <stdint.h>
#include <math.h>

#define BB 16
#define NTOT 21824
#define TOPN 1000
#define MAXOBJ 100
#define CAND_CAP 4096
#define NBUCKET 16384      // score < 1.0 -> (bits>>16) <= 0x3F7F < 16384
#define DPITCH 84          // smem row pitch (floats); %4==0 -> .128 conflict-free both ways

// ---------------- scratch (static device globals; zero-initialized at load) ----------------
__device__ uint32_t d_scoreBits[BB * NTOT];
__device__ int      d_cls[BB * NTOT];
__device__ uint32_t d_hist[BB * NBUCKET];          // cleared by k_select after use
__device__ float    d_topS[BB * TOPN];
__device__ int      d_topC[BB * TOPN];
__device__ float4   d_topB[BB * TOPN];
__device__ float    d_area[BB * TOPN];
__device__ uint32_t d_validW[BB * 32];
__device__ uint32_t d_mask[BB * TOPN * 32];        // zero rows are never written (stay 0)
__device__ uint32_t d_rnz[BB * 32];                // row-has-nonzero-mask bitmap

struct Ptrs {
    const float* cls[5];
    const float* reg[5];
    const float* ctr[5];
    const float* pos[5];
};

__constant__ int c_HW[5]   = {16384, 4096, 1024, 256, 64};
__constant__ int c_SH[5]   = {14, 12, 10, 8, 6};          // log2(HW)
__constant__ int c_OFF[5]  = {0, 16384, 20480, 21504, 21760};

// ---------------- decode: thread per anchor via SMEM transpose; no warp collectives ----------------
__global__ void __launch_bounds__(128) k_decode(Ptrs p) {
    __shared__ float sm[128 * DPITCH];   // 43008 B
    int blk = blockIdx.x;
    int t = threadIdx.x;

    int lvl, fStart;
    if (blk < 2048)      { lvl = 0; fStart = blk * 128; }
    else if (blk < 2560) { lvl = 1; fStart = (blk - 2048) * 128; }
    else if (blk < 2688) { lvl = 2; fStart = (blk - 2560) * 128; }
    else if (blk < 2720) { lvl = 3; fStart = (blk - 2688) * 128; }
    else                 { lvl = 4; fStart = (blk - 2720) * 128; }

    // stage 128 anchors x 80 floats, coalesced float4 loads
    const float4* src = (const float4*)(p.cls[lvl] + (size_t)fStart * 80);
    #pragma unroll
    for (int i = 0; i < 20; i++) {
        int idx = i * 128 + t;           // float4 index in chunk (20 per anchor)
        float4 v = src[idx];
        int a  = idx / 20;
        int k4 = idx - a * 20;
        *(float4*)&sm[a * DPITCH + k4 * 4] = v;
    }
    int f = fStart + t;
    float ctr = p.ctr[lvl][f];
    __syncthreads();

    // per-thread argmax over 80 values: 4 independent chains, exact first-index tiebreak
    const float* row = &sm[t * DPITCH];
    float m0 = -1.f, m1 = -1.f, m2 = -1.f, m3 = -1.f;
    int   i0 = 0, i1 = 1, i2 = 2, i3 = 3;
    #pragma unroll
    for (int j = 0; j < 20; j++) {
        float4 v = *(const float4*)&row[4 * j];
        if (v.x > m0) { m0 = v.x; i0 = 4 * j; }
        if (v.y > m1) { m1 = v.y; i1 = 4 * j + 1; }
        if (v.z > m2) { m2 = v.z; i2 = 4 * j + 2; }
        if (v.w > m3) { m3 = v.w; i3 = 4 * j + 3; }
    }
    float m = m0; int mi = i0;
    if (m1 > m || (m1 == m && i1 < mi)) { m = m1; mi = i1; }
    if (m2 > m || (m2 == m && i2 < mi)) { m = m2; mi = i2; }
    if (m3 > m || (m3 == m && i3 < mi)) { m = m3; mi = i3; }

    int b  = f >> c_SH[lvl];
    int hw = f - (b << c_SH[lvl]);
    int g  = b * NTOT + c_OFF[lvl] + hw;
    float s = __fsqrt_rn(m * ctr);
    uint32_t bits = __float_as_uint(s);
    d_scoreBits[g] = bits;
    d_cls[g] = mi;
    uint32_t bk = bits >> 16;
    if (bk >= NBUCKET) bk = NBUCKET - 1;
    atomicAdd(&d_hist[b * NBUCKET + bk], 1u);
}

// ---------------- per-batch: pivot + collect + sort + emit top-1000 (gathers boxes) ----------------
__global__ void __launch_bounds__(1024, 1) k_select(Ptrs p) {
    __shared__ unsigned long long sk[CAND_CAP];
    __shared__ uint32_t sA[1024], sB[1024];
    __shared__ uint32_t svalid[32];
    __shared__ uint32_t shCnt;
    __shared__ uint32_t shPivot;
    __shared__ int shChunk;

    int b = blockIdx.x;
    int t = threadIdx.x;   // 1024
    uint32_t* h = &d_hist[b * NBUCKET];

    #pragma unroll
    for (int i = t; i < CAND_CAP; i += 1024) sk[i] = 0ULL;
    if (t == 0) shCnt = 0u;
    if (t < 32) { svalid[t] = 0u; d_rnz[b * 32 + t] = 0u; }

    // chunk sums: thread t owns buckets [t*16, t*16+16)
    {
        uint32_t s = 0;
        const uint4* hv = (const uint4*)(h + t * 16);
        #pragma unroll
        for (int q = 0; q < 4; q++) {
            uint4 v = hv[q];
            s += v.x + v.y + v.z + v.w;
        }
        sA[t] = s;
    }
    __syncthreads();

    // parallel inclusive suffix scan over 1024 chunk sums (Hillis-Steele, ping-pong)
    uint32_t* src = sA; uint32_t* dst = sB;
    #pragma unroll
    for (int off = 1; off < 1024; off <<= 1) {
        uint32_t v = src[t] + ((t + off < 1024) ? src[t + off] : 0u);
        dst[t] = v;
        __syncthreads();
        uint32_t* tmp = src; src = dst; dst = tmp;
    }

    if (src[t] >= TOPN && (t == 1023 || src[t + 1] < TOPN)) shChunk = t;
    __syncthreads();
    if (t == 0) {
        int c = shChunk;
        uint32_t run = (c < 1023) ? src[c + 1] : 0u;
        uint32_t piv = (uint32_t)(c * 16);
        for (int v = c * 16 + 15; v >= c * 16; v--) {
            run += h[v];
            if (run >= TOPN) { piv = (uint32_t)v; break; }
        }
        shPivot = piv;
    }
    __syncthreads();
    uint32_t pivot = shPivot;

    // zero hist slice for next replay
    {
        uint4 z = make_uint4(0u, 0u, 0u, 0u);
        ((uint4*)(h + t * 16))[0] = z;
        ((uint4*)(h + t * 16))[1] = z;
        ((uint4*)(h + t * 16))[2] = z;
        ((uint4*)(h + t * 16))[3] = z;
    }

    // collect candidates >= pivot into shared
    const uint32_t* sbits = &d_scoreBits[b * NTOT];
    for (int i = t; i < NTOT; i += 1024) {
        uint32_t bits = sbits[i];
        if ((bits >> 16) >= pivot) {
            uint32_t slot = atomicAdd(&shCnt, 1u);
            if (slot < CAND_CAP)
                sk[slot] = ((unsigned long long)bits << 15) |
                           (unsigned long long)(32767 - i);
        }
    }
    __syncthreads();

    uint32_t cnt = shCnt;
    if (cnt > CAND_CAP) cnt = CAND_CAP;
    int sortN = 1024;
    while (sortN < (int)cnt) sortN <<= 1;

    // bitonic sort, descending
    for (int k = 2; k <= sortN; k <<= 1) {
        for (int j = k >> 1; j > 0; j >>= 1) {
            for (int i = t; i < sortN; i += 1024) {
                int ix = i ^ j;
                if (ix > i) {
                    bool dir = ((i & k) == 0);
                    unsigned long long A = sk[i], Bv = sk[ix];
                    if ((A < Bv) == dir) { sk[i] = Bv; sk[ix] = A; }
                }
            }
            __syncthreads();
        }
    }

    // emit top-1000: gather reg/pos for winners and build boxes here
    if (t < TOPN) {
        unsigned long long key = sk[t];
        float s; int c; float4 bx;
        int a = 32767 - (int)(key & 0x7FFFULL);
        if (key == 0ULL || a < 0 || a >= NTOT) {
            s = -1e30f; c = 0; bx = make_float4(0.f, 0.f, 0.f, 0.f);
        } else {
            s = __uint_as_float((uint32_t)(key >> 15));
            c = d_cls[b * NTOT + a];
            int lvl, hw;
            if (a < 16384)      { lvl = 0; hw = a; }
            else if (a < 20480) { lvl = 1; hw = a - 16384; }
            else if (a < 21504) { lvl = 2; hw = a - 20480; }
            else if (a < 21760) { lvl = 3; hw = a - 21504; }
            else                { lvl = 4; hw = a - 21760; }
            int base = b * c_HW[lvl] + hw;
            float4 rr = ((const float4*)p.reg[lvl])[base];
            float2 pp = ((const float2*)p.pos[lvl])[base];
            bx.x = truncf(pp.x - rr.x);
            bx.y = truncf(pp.y - rr.y);
            bx.z = truncf(pp.x + rr.z);
            bx.w = truncf(pp.y + rr.w);
        }
        d_topS[b * TOPN + t] = s;
        d_topC[b * TOPN + t] = c;
        d_topB[b * TOPN + t] = bx;
        float w = bx.z - bx.x, hh = bx.w - bx.y;
        d_area[b * TOPN + t] = fmaxf(w * hh, 1e-4f);
        if (s > 0.05f) atomicOr(&svalid[t >> 5], 1u << (t & 31));
    }
    __syncthreads();
    if (t < 32) d_validW[b * 32 + t] = svalid[t];
}

// ---------------- IoU mask matrix: grid (B, 32), 1024 threads ----------------
__global__ void __launch_bounds__(1024, 1) k_mask() {
    __shared__ float4 sb[TOPN];
    __shared__ float  sa[TOPN];
    __shared__ uint32_t sv[32];
    int b = blockIdx.x;
    int rb = blockIdx.y;
    int t = threadIdx.x;
    for (int i = t; i < TOPN; i += 1024) {
        sb[i] = d_topB[b * TOPN + i];
        sa[i] = d_area[b * TOPN + i];
    }
    if (t < 32) sv[t] = d_validW[b * 32 + t];
    __syncthreads();

    int lane = t & 31, w = t >> 5;
    int rbase = rb * 32;
    int rend = rbase + 32; if (rend > TOPN) rend = TOPN;
    for (int i = rbase + w; i < rend; i += 32) {
        bool vi = (sv[i >> 5] >> (i & 31)) & 1u;
        if (!vi) continue;   // whole row is zero; never written, stays 0
        float4 bi = sb[i];
        float ai = sa[i];
        uint32_t anyrow = 0u;
        int jw0 = i >> 5;
        #pragma unroll 4
        for (int jw = jw0; jw < 32; jw++) {
            int j = jw * 32 + lane;
            bool pred = false;
            if (j < TOPN && j > i) {
                float tlx = fmaxf(bi.x, sb[j].x), tly = fmaxf(bi.y, sb[j].y);
                float brx = fminf(bi.z, sb[j].z), bry = fminf(bi.w, sb[j].w);
                float ow = fmaxf(brx - tlx, 0.f), oh = fmaxf(bry - tly, 0.f);
                float inter = ow * oh;
                float uni = fmaxf(ai + sa[j] - inter, 1e-4f);
                pred = (inter / uni) >= 0.6f;
            }
            uint32_t m = __ballot_sync(0xffffffffu, pred);
            anyrow |= m;
            if (lane == 0) d_mask[(b * TOPN + i) * 32 + jw] = m;
        }
        if (lane == 0 && anyrow)
            atomicOr(&d_rnz[b * 32 + (i >> 5)], 1u << (i & 31));
    }
}

// ---------------- serial suppression + PARALLEL output scatter: grid B, 512 threads ----------------
__global__ void __launch_bounds__(512, 1) k_nms(float* out) {
    extern __shared__ uint32_t shm[];            // compacted rows: nrnz x 32 words
    __shared__ uint32_t sRnz[32];
    __shared__ uint32_t sBase[33];
    __shared__ uint16_t rowOfSlot[TOPN];
    __shared__ uint32_t sKw[32];                 // keep words
    __shared__ uint32_t sRank[32];               // start rank per keep word
    int b = blockIdx.x;
    int t = threadIdx.x;
    int lane = t & 31;

    if (t < 32) sRnz[t] = d_rnz[b * 32 + t];

    // init outputs for this batch
    for (int k = t; k < 100; k += 512) {
        out[b * 100 + k] = -1.0f;               // scores
        out[1600 + b * 100 + k] = -1.0f;        // classes
    }
    for (int k = t; k < 400; k += 512)
        out[3200 + b * 400 + k] = 0.0f;         // boxes
    __syncthreads();

    // warp 0: exclusive scan of popcounts -> sBase
    if (t < 32) {
        int pc = __popc(sRnz[t]);
        int pre = pc;
        #pragma unroll
        for (int off = 1; off < 32; off <<= 1) {
            int n = __shfl_up_sync(0xffffffffu, pre, off);
            if (t >= off) pre += n;
        }
        sBase[t] = (uint32_t)(pre - pc);
        if (t == 31) sBase[32] = (uint32_t)pre;
    }
    __syncthreads();
    int nrnz = (int)sBase[32];

    // parallel slot map: strided over all TOPN rows
    for (int i = t; i < TOPN; i += 512) {
        uint32_t wbits = sRnz[i >> 5];
        if ((wbits >> (i & 31)) & 1u) {
            int slot = (int)sBase[i >> 5] + __popc(wbits & ((1u << (i & 31)) - 1u));
            rowOfSlot[slot] = (uint16_t)i;
        }
    }
    __syncthreads();

    // stage compacted rows: uint4-coalesced, all 512 threads
    {
        uint4* shv = (uint4*)shm;
        const uint4* gm = (const uint4*)&d_mask[b * TOPN * 32];
        int tot = nrnz * 8;
        for (int i = t; i < tot; i += 512)
            shv[i] = gm[(int)rowOfSlot[i >> 3] * 8 + (i & 7)];
    }
    __syncthreads();

    // ---- warp 0: serial suppression ----
    if (t < 32) {
        uint32_t myRnz = sRnz[lane];

        // diagonal prefetch: dwreg[bw] = row (bw*32+lane)'s word bw (0 if row has no mask)
        uint32_t dwreg[32];
        #pragma unroll
        for (int bw = 0; bw < 32; bw++) {
            uint32_t rw = sRnz[bw];
            uint32_t has = (rw >> lane) & 1u;
            uint32_t slot = sBase[bw] + __popc(rw & ((1u << lane) - 1u));
            dwreg[bw] = has ? shm[slot * 32 + bw] : 0u;
        }

        uint32_t supp = 0;
        for (int bw = 0; bw < 32; bw++) {
            uint32_t sw = __shfl_sync(0xffffffffu, supp, bw);
            uint32_t dw = dwreg[bw];
            uint32_t conflict = __ballot_sync(0xffffffffu, dw != 0u) & ~sw;
            uint32_t active;
            if (!conflict) {
                active = ~sw;
            } else {
                active = ~sw;
                uint32_t rem = conflict;
                while (rem) {
                    int hrow = __ffs(rem) - 1;
                    rem &= rem - 1;
                    uint32_t dwh = __shfl_sync(0xffffffffu, dw, hrow);
                    if ((active >> hrow) & 1u) {
                        active &= ~dwh;
                        rem &= ~dwh;
                    }
                }
            }
            if (bw == 31) active &= 0xFFu;   // rows >= 1000 don't exist
            // rz/bbase via LDS (off the supp critical chain)
            uint32_t rz = sRnz[bw];
            uint32_t bbase = sBase[bw];
            uint32_t need = active & rz;
            while (need) {
                int r0 = __ffs(need) - 1;
                need &= need - 1;
                uint32_t s0 = bbase + __popc(rz & ((1u << r0) - 1u));
                uint32_t v = shm[s0 * 32 + lane];
                if (need) {
                    int r1 = __ffs(need) - 1;
                    need &= need - 1;
                    uint32_t s1 = bbase + __popc(rz & ((1u << r1) - 1u));
                    v |= shm[s1 * 32 + lane];
                }
                supp |= v;
            }
        }

        uint32_t kw = d_validW[b * 32 + lane] & ~supp;

        // exclusive scan of keep-counts across lanes
        int pc = __popc(kw);
        int pre = pc;
        #pragma unroll
        for (int off = 1; off < 32; off <<= 1) {
            int n = __shfl_up_sync(0xffffffffu, pre, off);
            if (lane >= off) pre += n;
        }
        sKw[lane] = kw;
        sRank[lane] = (uint32_t)(pre - pc);   // start rank for this word
    }
    __syncthreads();

    // ---- all 512 threads: parallel output scatter ----
    for (int i = t; i < TOPN; i += 512) {
        uint32_t word = sKw[i >> 5];
        if ((word >> (i & 31)) & 1u) {
            int r = (int)sRank[i >> 5] + __popc(word & ((1u << (i & 31)) - 1u));
            if (r < MAXOBJ) {
                out[b * 100 + r] = d_topS[b * TOPN + i];
                out[1600 + b * 100 + r] = (float)d_topC[b * TOPN + i];
                float4 bx = d_topB[b * TOPN + i];
                float* ob = out + 3200 + (b * 100 + r) * 4;
                ob[0] = bx.x; ob[1] = bx.y; ob[2] = bx.z; ob[3] = bx.w;
            }
        }
    }
}

// ---------------- host launch ----------------
extern "C" void kernel_launch(void* const* d_in, const int* in_sizes, int n_in,
                              void* d_out, int out_size) {
    (void)n_in; (void)out_size;
    const int HW0 = 16384;
    Ptrs P;
    bool dictOrder = (in_sizes[1] == BB * HW0 * 4);  // reg0 right after cls0?
    if (dictOrder) {
        for (int l = 0; l < 5; l++) {
            P.cls[l] = (const float*)d_in[l * 4 + 0];
            P.reg[l] = (const float*)d_in[l * 4 + 1];
            P.ctr[l] = (const float*)d_in[l * 4 + 2];
            P.pos[l] = (const float*)d_in[l * 4 + 3];
        }
    } else {
        for (int l = 0; l < 5; l++) {
            P.cls[l] = (const float*)d_in[l];
            P.reg[l] = (const float*)d_in[5 + l];
            P.ctr[l] = (const float*)d_in[10 + l];
            P.pos[l] = (const float*)d_in[15 + l];
        }
    }

    float* out = (float*)d_out;

    static const size_t NMS_SHM = (size_t)TOPN * 32 * sizeof(uint32_t);
    cudaFuncSetAttribute(k_nms, cudaFuncAttributeMaxDynamicSharedMemorySize,
                         (int)NMS_SHM);

    // decode: per-level block counts 2048/512/128/32/8 = 2728 blocks of 128
    k_decode<<<2728, 128>>>(P);
    k_select<<<BB, 1024>>>(P);
    dim3 mg(BB, 32);
    k_mask<<<mg, 1024>>>();
    k_nms<<<BB, 512, NMS_SHM>>>(out);
}